// round 10
// baseline (speedup 1.0000x reference)
#include <cuda_runtime.h>
#include <cstdint>

#define N_NODES 5120
#define N_EDGES 163840
#define TBLD    256
#define LAT     128
#define NG      64
#define NN      80
#define N2      6400
#define H1      12800

// ---------------- scratch (no allocs allowed) ----------------
__device__ __align__(128) float g_h [N_NODES * LAT];
__device__ __align__(128) float g_z2[NG * N2];
__device__ __align__(128) float g_z3[NG * H1];
__device__ __align__(128) float g_p1[5][NG * H1];    // GEMM1 split-K partials
__device__ __align__(128) float g_p2[11][NG * N2];   // GEMM2 split-K partials
__device__ int   g_deg[N_NODES];
__device__ int   g_cur[N_NODES];
__device__ int   g_row[N_NODES];
__device__ float g_dinv[N_NODES];
__device__ int   g_csr[N_EDGES];

// ---------------- stage 1: clear counters + h = x @ Wg (merged) --------------
__global__ void k_prep(const float* __restrict__ x, const float* __restrict__ Wg) {
    if (blockIdx.x >= 160) {   // clear part
        int i = (blockIdx.x - 160) * 256 + threadIdx.x;
        if (i < N_NODES) { g_deg[i] = 0; g_cur[i] = 0; }
        return;
    }
    __shared__ float Xs[32][33];
    __shared__ float Ws[32][128];
    int tid = threadIdx.x;
    int m0  = blockIdx.x * 32;
    int tm  = (tid >> 5) * 4;
    int tn  = (tid & 31) * 4;
    float acc[4][4] = {};
    for (int k0 = 0; k0 < TBLD; k0 += 32) {
        int r = tid >> 3, c = (tid & 7) * 4;
        float4 xv = *(const float4*)&x[(m0 + r) * TBLD + k0 + c];
        Xs[r][c] = xv.x; Xs[r][c + 1] = xv.y; Xs[r][c + 2] = xv.z; Xs[r][c + 3] = xv.w;
#pragma unroll
        for (int i = 0; i < 4; i++) {
            int idx = tid + i * 256;
            int wr = idx >> 5, wc = (idx & 31) * 4;
            *(float4*)&Ws[wr][wc] = *(const float4*)&Wg[(k0 + wr) * LAT + wc];
        }
        __syncthreads();
#pragma unroll
        for (int kk = 0; kk < 32; kk++) {
            float a0 = Xs[tm][kk], a1 = Xs[tm + 1][kk], a2 = Xs[tm + 2][kk], a3 = Xs[tm + 3][kk];
            float4 bv = *(float4*)&Ws[kk][tn];
            acc[0][0] += a0 * bv.x; acc[0][1] += a0 * bv.y; acc[0][2] += a0 * bv.z; acc[0][3] += a0 * bv.w;
            acc[1][0] += a1 * bv.x; acc[1][1] += a1 * bv.y; acc[1][2] += a1 * bv.z; acc[1][3] += a1 * bv.w;
            acc[2][0] += a2 * bv.x; acc[2][1] += a2 * bv.y; acc[2][2] += a2 * bv.z; acc[2][3] += a2 * bv.w;
            acc[3][0] += a3 * bv.x; acc[3][1] += a3 * bv.y; acc[3][2] += a3 * bv.z; acc[3][3] += a3 * bv.w;
        }
        __syncthreads();
    }
#pragma unroll
    for (int i = 0; i < 4; i++) {
        float4 v = make_float4(acc[i][0], acc[i][1], acc[i][2], acc[i][3]);
        *(float4*)&g_h[(m0 + tm + i) * LAT + tn] = v;
    }
}

// ---------------- stage 2: degree histogram over dst (4 edges/thread) --------
__global__ void k_deg(const int* __restrict__ ei) {
    int t = blockIdx.x * 256 + threadIdx.x;            // 160 blocks
    const int4* d4 = (const int4*)(ei + N_EDGES);
    int4 d = d4[t];
    atomicAdd(&g_deg[d.x], 1);
    atomicAdd(&g_deg[d.y], 1);
    atomicAdd(&g_deg[d.z], 1);
    atomicAdd(&g_deg[d.w], 1);
}

// ---------------- stage 3: exclusive scan (shuffle) -> rowstart, dinv --------
__global__ void k_scan() {
    int tid = threadIdx.x, lane = tid & 31, wd = tid >> 5;
    int base = tid * 5;
    int d[5]; int s = 0;
#pragma unroll
    for (int i = 0; i < 5; i++) { d[i] = g_deg[base + i]; s += d[i]; }
    int tot = s;
#pragma unroll
    for (int off = 1; off < 32; off <<= 1) {
        int v = __shfl_up_sync(0xffffffffu, s, off);
        if (lane >= off) s += v;
    }
    __shared__ int ws[32];
    if (lane == 31) ws[wd] = s;
    __syncthreads();
    if (wd == 0) {
        int v = ws[lane];
#pragma unroll
        for (int off = 1; off < 32; off <<= 1) {
            int u = __shfl_up_sync(0xffffffffu, v, off);
            if (lane >= off) v += u;
        }
        ws[lane] = v;
    }
    __syncthreads();
    int pre = s - tot + (wd > 0 ? ws[wd - 1] : 0);
#pragma unroll
    for (int i = 0; i < 5; i++) {
        g_row[base + i]  = pre;
        pre += d[i];
        g_dinv[base + i] = d[i] > 0 ? rsqrtf((float)d[i]) : 0.f;
    }
}

// ---------------- stage 4: CSR fill (4 edges/thread) ----------------
__global__ void k_csr(const int* __restrict__ ei) {
    int t = blockIdx.x * 256 + threadIdx.x;            // 160 blocks
    const int4* s4 = (const int4*)ei;
    const int4* d4 = (const int4*)(ei + N_EDGES);
    int4 s = s4[t];
    int4 d = d4[t];
    int p0 = atomicAdd(&g_cur[d.x], 1);
    int p1 = atomicAdd(&g_cur[d.y], 1);
    int p2 = atomicAdd(&g_cur[d.z], 1);
    int p3 = atomicAdd(&g_cur[d.w], 1);
    g_csr[g_row[d.x] + p0] = s.x;
    g_csr[g_row[d.y] + p1] = s.y;
    g_csr[g_row[d.z] + p2] = s.z;
    g_csr[g_row[d.w] + p3] = s.w;
}

// ------- stage 5+6 merged: gather-aggregate + bias + relu, then z z^T --------
// one block per graph: 512 threads; gather 80 nodes into smem, then outer.
__global__ __launch_bounds__(512) void k_go(const float* __restrict__ bg) {
    __shared__ float Zs[NN][LAT + 1];    // stride 129: conflict-free for outer
    int b = blockIdx.x;
    int tid = threadIdx.x;
    int wid = tid >> 5, lane = tid & 31;
    const float4* h4 = (const float4*)g_h;
    float4 bv = ((const float4*)bg)[lane];

    for (int n = wid; n < NN; n += 16) {
        int node  = b * NN + n;
        int start = g_row[node];
        int cnt   = g_deg[node];
        float dd  = g_dinv[node];
        float4 a0 = {0,0,0,0}, a1 = {0,0,0,0}, a2 = {0,0,0,0}, a3 = {0,0,0,0};
        int j = 0;
        for (; j + 4 <= cnt; j += 4) {
            int s0 = g_csr[start + j],     s1 = g_csr[start + j + 1];
            int s2 = g_csr[start + j + 2], s3 = g_csr[start + j + 3];
            float w0 = g_dinv[s0], w1 = g_dinv[s1], w2 = g_dinv[s2], w3 = g_dinv[s3];
            float4 v0 = h4[s0 * 32 + lane], v1 = h4[s1 * 32 + lane];
            float4 v2 = h4[s2 * 32 + lane], v3 = h4[s3 * 32 + lane];
            a0.x += w0 * v0.x; a0.y += w0 * v0.y; a0.z += w0 * v0.z; a0.w += w0 * v0.w;
            a1.x += w1 * v1.x; a1.y += w1 * v1.y; a1.z += w1 * v1.z; a1.w += w1 * v1.w;
            a2.x += w2 * v2.x; a2.y += w2 * v2.y; a2.z += w2 * v2.z; a2.w += w2 * v2.w;
            a3.x += w3 * v3.x; a3.y += w3 * v3.y; a3.z += w3 * v3.z; a3.w += w3 * v3.w;
        }
        for (; j < cnt; j++) {
            int s0 = g_csr[start + j];
            float w0 = g_dinv[s0];
            float4 v0 = h4[s0 * 32 + lane];
            a0.x += w0 * v0.x; a0.y += w0 * v0.y; a0.z += w0 * v0.z; a0.w += w0 * v0.w;
        }
        float4 acc;
        acc.x = (a0.x + a1.x) + (a2.x + a3.x);
        acc.y = (a0.y + a1.y) + (a2.y + a3.y);
        acc.z = (a0.z + a1.z) + (a2.z + a3.z);
        acc.w = (a0.w + a1.w) + (a2.w + a3.w);
        int c = lane * 4;
        Zs[n][c]     = fmaxf(acc.x * dd + bv.x, 0.f);
        Zs[n][c + 1] = fmaxf(acc.y * dd + bv.y, 0.f);
        Zs[n][c + 2] = fmaxf(acc.z * dd + bv.z, 0.f);
        Zs[n][c + 3] = fmaxf(acc.w * dd + bv.w, 0.f);
    }
    __syncthreads();

    if (tid < 256) {
        int rn = (tid >> 4) * 5;
        int rm = (tid & 15) * 5;
        float acc[5][5] = {};
        for (int l = 0; l < LAT; l++) {
            float a[5], bb[5];
#pragma unroll
            for (int i = 0; i < 5; i++) a[i]  = Zs[rn + i][l];
#pragma unroll
            for (int j = 0; j < 5; j++) bb[j] = Zs[rm + j][l];
#pragma unroll
            for (int i = 0; i < 5; i++)
#pragma unroll
                for (int j = 0; j < 5; j++) acc[i][j] += a[i] * bb[j];
        }
#pragma unroll
        for (int i = 0; i < 5; i++)
#pragma unroll
            for (int j = 0; j < 5; j++)
                g_z2[b * N2 + (rn + i) * NN + (rm + j)] = acc[i][j];
    }
}

// ======================= tf32 mma.sync GEMM (R7-proven loop) =================
__device__ __forceinline__ uint32_t sptr(const void* p) {
    return (uint32_t)__cvta_generic_to_shared(p);
}
__device__ __forceinline__ void cp16(uint32_t s, const void* g) {
    asm volatile("cp.async.cg.shared.global [%0], [%1], 16;" :: "r"(s), "l"(g));
}
__device__ __forceinline__ void mma8(float* c, const uint32_t* a, const uint32_t* b) {
    asm volatile(
        "mma.sync.aligned.m16n8k8.row.col.f32.tf32.tf32.f32 "
        "{%0,%1,%2,%3}, {%4,%5,%6,%7}, {%8,%9}, {%0,%1,%2,%3};"
        : "+f"(c[0]), "+f"(c[1]), "+f"(c[2]), "+f"(c[3])
        : "r"(a[0]), "r"(a[1]), "r"(a[2]), "r"(a[3]), "r"(b[0]), "r"(b[1]));
}

// smem layout (floats), 3 stages:
//   As: 3 stages x 64 rows x 20 (16 used + 4 pad)
//   Bs: 3 stages x 16 rows x 264 (256 used + 8 pad)
#define A_ROW   20
#define A_STG   (64 * A_ROW)          // 1280
#define B_ROW   264
#define B_STG   (16 * B_ROW)          // 4224
#define B_OFF   (3 * A_STG)
#define MM_SMEM ((3 * A_STG + 3 * B_STG) * 4)   // 66048 bytes

// CTA: 64(M) x 256(N), 8 warps (2x4), warp tile 32x64, K_CHUNK=16, 3 stages.
template<int MODE>
__global__ __launch_bounds__(256, 2) void k_mm(const float* __restrict__ W) {
    constexpr int K    = (MODE == 1) ? N2 : H1;
    constexpr int NOUT = (MODE == 1) ? H1 : N2;
    constexpr int NSPL = (MODE == 1) ? 5 : 11;   // 250 / 275 CTAs: ONE wave @ 2/SM
    const float* A = (MODE == 1) ? g_z2 : g_z3;
    float* outp    = (MODE == 1) ? g_p1[blockIdx.y] : g_p2[blockIdx.y];

    extern __shared__ float sm[];
    float* As = sm;
    float* Bs = sm + B_OFF;

    const int tid = threadIdx.x;
    const int n0  = blockIdx.x * 256;
    const int sp  = blockIdx.y;

    constexpr int TOT = K / 16;
    constexpr int per = TOT / NSPL, rem = TOT % NSPL;
    const int ks0 = sp * per + min(sp, rem);
    const int cnt = per + (sp < rem ? 1 : 0);

    const int lane = tid & 31, wp = tid >> 5;
    const int wm = wp >> 2, wn = wp & 3;      // 2 x 4 warp grid
    const int gq = lane >> 2, tq = lane & 3;

    const int a_r = tid >> 2, a_c4 = (tid & 3) * 4;
    const uint32_t a_dst0 = sptr(As) + (uint32_t)(a_r * A_ROW + a_c4) * 4;
    const uint32_t b_base = sptr(Bs);

    auto issue = [&](int st, int ki) {
        int kk = (ks0 + ki) * 16;
        cp16(a_dst0 + (uint32_t)(st * A_STG) * 4, A + (size_t)a_r * K + kk + a_c4);
#pragma unroll
        for (int q = 0; q < 4; q++) {
            int id = tid + q * 256;
            int r  = id >> 6, c4 = (id & 63) * 4;
            cp16(b_base + (uint32_t)(st * B_STG + r * B_ROW + c4) * 4,
                 W + (size_t)(kk + r) * NOUT + n0 + c4);
        }
    };

    float C[2][8][4] = {};

    issue(0, 0); asm volatile("cp.async.commit_group;");
    if (cnt > 1) issue(1, 1);
    asm volatile("cp.async.commit_group;");

    for (int i = 0; i < cnt; i++) {
        asm volatile("cp.async.wait_group 1;");
        __syncthreads();
        const int st = i % 3;
        const float* as = As + st * A_STG;
        const float* bs = Bs + st * B_STG;
#pragma unroll
        for (int s8 = 0; s8 < 2; s8++) {
            uint32_t a[2][4], b[8][2];
            int kc = 8 * s8;
#pragma unroll
            for (int mi = 0; mi < 2; mi++) {
                int r = wm * 32 + mi * 16 + gq;
                a[mi][0] = __float_as_uint(as[r * A_ROW + kc + tq]);
                a[mi][1] = __float_as_uint(as[(r + 8) * A_ROW + kc + tq]);
                a[mi][2] = __float_as_uint(as[r * A_ROW + kc + tq + 4]);
                a[mi][3] = __float_as_uint(as[(r + 8) * A_ROW + kc + tq + 4]);
            }
#pragma unroll
            for (int ni = 0; ni < 8; ni++) {
                int c = wn * 64 + ni * 8 + gq;
                b[ni][0] = __float_as_uint(bs[(kc + tq) * B_ROW + c]);
                b[ni][1] = __float_as_uint(bs[(kc + tq + 4) * B_ROW + c]);
            }
#pragma unroll
            for (int mi = 0; mi < 2; mi++)
#pragma unroll
                for (int ni = 0; ni < 8; ni++)
                    mma8(C[mi][ni], a[mi], b[ni]);
        }
        int nx = i + 2;
        if (nx < cnt) issue(nx % 3, nx);
        asm volatile("cp.async.commit_group;");
    }

    // write split-K partials (summed in epilogue)
#pragma unroll
    for (int mi = 0; mi < 2; mi++)
#pragma unroll
        for (int ni = 0; ni < 8; ni++) {
            int r = wm * 32 + mi * 16 + gq;
            int c = n0 + wn * 64 + ni * 8 + 2 * tq;
            *(float2*)&outp[(size_t)r * NOUT + c]       = make_float2(C[mi][ni][0], C[mi][ni][1]);
            *(float2*)&outp[(size_t)(r + 8) * NOUT + c] = make_float2(C[mi][ni][2], C[mi][ni][3]);
        }
}

// ---------------- epilogues (float4, sum partials + bias + act) --------------
__global__ void k_epi1(const float* __restrict__ b1) {
    int g = blockIdx.x * 256 + threadIdx.x;      // float4 index
    int e = g * 4;
    float4 v = *(const float4*)&g_p1[0][e];
#pragma unroll
    for (int s = 1; s < 5; s++) {
        float4 p = *(const float4*)&g_p1[s][e];
        v.x += p.x; v.y += p.y; v.z += p.z; v.w += p.w;
    }
    float4 bb = *(const float4*)&b1[e % H1];
    v.x = fmaxf(v.x + bb.x, 0.f); v.y = fmaxf(v.y + bb.y, 0.f);
    v.z = fmaxf(v.z + bb.z, 0.f); v.w = fmaxf(v.w + bb.w, 0.f);
    *(float4*)&g_z3[e] = v;
}
__global__ void k_epi2(const float* __restrict__ b2, float* __restrict__ out) {
    int g = blockIdx.x * 256 + threadIdx.x;
    int e = g * 4;
    float4 v = *(const float4*)&g_p2[0][e];
#pragma unroll
    for (int s = 1; s < 11; s++) {
        float4 p = *(const float4*)&g_p2[s][e];
        v.x += p.x; v.y += p.y; v.z += p.z; v.w += p.w;
    }
    float4 bb = *(const float4*)&b2[e % N2];
    v.x += bb.x; v.y += bb.y; v.z += bb.z; v.w += bb.w;
    float4 o;
    o.x = 1.f / (1.f + __expf(-v.x));
    o.y = 1.f / (1.f + __expf(-v.y));
    o.z = 1.f / (1.f + __expf(-v.z));
    o.w = 1.f / (1.f + __expf(-v.w));
    *(float4*)&out[e] = o;
}

// ---------------- launch ----------------
extern "C" void kernel_launch(void* const* d_in, const int* in_sizes, int n_in,
                              void* d_out, int out_size) {
    const float* x  = (const float*)d_in[0];
    const int*   ei = (const int*)  d_in[1];
    const float* Wg = (const float*)d_in[2];
    const float* bg = (const float*)d_in[3];
    const float* W1 = (const float*)d_in[4];
    const float* b1 = (const float*)d_in[5];
    const float* W2 = (const float*)d_in[6];
    const float* b2 = (const float*)d_in[7];
    float* out = (float*)d_out;

    static bool attr_done = false;
    if (!attr_done) {
        cudaFuncSetAttribute(k_mm<1>, cudaFuncAttributeMaxDynamicSharedMemorySize, MM_SMEM);
        cudaFuncSetAttribute(k_mm<2>, cudaFuncAttributeMaxDynamicSharedMemorySize, MM_SMEM);
        attr_done = true;
    }

    k_prep  <<<180, 256>>>(x, Wg);
    k_deg   <<<160, 256>>>(ei);
    k_scan  <<<1, 1024>>>();
    k_csr   <<<160, 256>>>(ei);
    k_go    <<<64, 512>>>(bg);
    k_mm<1> <<<dim3(50, 5),  256, MM_SMEM>>>(W1);   // 250 CTAs: one wave @ 2/SM
    k_epi1  <<<NG * H1 / 1024, 256>>>(b1);
    k_mm<2> <<<dim3(25, 11), 256, MM_SMEM>>>(W2);   // 275 CTAs: one wave @ 2/SM
    k_epi2  <<<NG * N2 / 1024, 256>>>(b2, out);
}

// round 11
// speedup vs baseline: 1.2163x; 1.2163x over previous
#include <cuda_runtime.h>
#include <cuda_fp16.h>
#include <cstdint>

#define N_NODES 5120
#define N_EDGES 163840
#define TBLD    256
#define LAT     128
#define NG      64
#define NN      80
#define N2      6400
#define H1      12800

// ---------------- scratch (no allocs allowed) ----------------
__device__ __align__(128) float  g_h  [N_NODES * LAT];
__device__ __align__(128) float  g_z  [N_NODES * LAT];
__device__ __align__(128) __half g_z2h[NG * N2];     // GEMM1 A (fp16)
__device__ __align__(128) __half g_z3h[NG * H1];     // GEMM2 A (fp16)
__device__ __align__(128) float  g_p1[6][NG * H1];   // GEMM1 split-K partials
__device__ __align__(128) float  g_p2[12][NG * N2];  // GEMM2 split-K partials
__device__ int   g_deg[N_NODES];
__device__ int   g_cur[N_NODES];
__device__ int   g_row[N_NODES];
__device__ float g_dinv[N_NODES];
__device__ int   g_csr[N_EDGES];

// ---------------- stage 1: clear counters + h = x @ Wg (merged) --------------
__global__ void k_prep(const float* __restrict__ x, const float* __restrict__ Wg) {
    if (blockIdx.x >= 160) {   // clear part
        int i = (blockIdx.x - 160) * 256 + threadIdx.x;
        if (i < N_NODES) { g_deg[i] = 0; g_cur[i] = 0; }
        return;
    }
    __shared__ float Xs[32][33];
    __shared__ float Ws[32][128];
    int tid = threadIdx.x;
    int m0  = blockIdx.x * 32;
    int tm  = (tid >> 5) * 4;
    int tn  = (tid & 31) * 4;
    float acc[4][4] = {};
    for (int k0 = 0; k0 < TBLD; k0 += 32) {
        int r = tid >> 3, c = (tid & 7) * 4;
        float4 xv = *(const float4*)&x[(m0 + r) * TBLD + k0 + c];
        Xs[r][c] = xv.x; Xs[r][c + 1] = xv.y; Xs[r][c + 2] = xv.z; Xs[r][c + 3] = xv.w;
#pragma unroll
        for (int i = 0; i < 4; i++) {
            int idx = tid + i * 256;
            int wr = idx >> 5, wc = (idx & 31) * 4;
            *(float4*)&Ws[wr][wc] = *(const float4*)&Wg[(k0 + wr) * LAT + wc];
        }
        __syncthreads();
#pragma unroll
        for (int kk = 0; kk < 32; kk++) {
            float a0 = Xs[tm][kk], a1 = Xs[tm + 1][kk], a2 = Xs[tm + 2][kk], a3 = Xs[tm + 3][kk];
            float4 bv = *(float4*)&Ws[kk][tn];
            acc[0][0] += a0 * bv.x; acc[0][1] += a0 * bv.y; acc[0][2] += a0 * bv.z; acc[0][3] += a0 * bv.w;
            acc[1][0] += a1 * bv.x; acc[1][1] += a1 * bv.y; acc[1][2] += a1 * bv.z; acc[1][3] += a1 * bv.w;
            acc[2][0] += a2 * bv.x; acc[2][1] += a2 * bv.y; acc[2][2] += a2 * bv.z; acc[2][3] += a2 * bv.w;
            acc[3][0] += a3 * bv.x; acc[3][1] += a3 * bv.y; acc[3][2] += a3 * bv.z; acc[3][3] += a3 * bv.w;
        }
        __syncthreads();
    }
#pragma unroll
    for (int i = 0; i < 4; i++) {
        float4 v = make_float4(acc[i][0], acc[i][1], acc[i][2], acc[i][3]);
        *(float4*)&g_h[(m0 + tm + i) * LAT + tn] = v;
    }
}

// ---------------- stage 2: degree histogram over dst (4 edges/thread) --------
__global__ void k_deg(const int* __restrict__ ei) {
    int t = blockIdx.x * 256 + threadIdx.x;            // 160 blocks
    const int4* d4 = (const int4*)(ei + N_EDGES);
    int4 d = d4[t];
    atomicAdd(&g_deg[d.x], 1);
    atomicAdd(&g_deg[d.y], 1);
    atomicAdd(&g_deg[d.z], 1);
    atomicAdd(&g_deg[d.w], 1);
}

// ---------------- stage 3: exclusive scan (shuffle) -> rowstart, dinv --------
__global__ void k_scan() {
    int tid = threadIdx.x, lane = tid & 31, wd = tid >> 5;
    int base = tid * 5;
    int d[5]; int s = 0;
#pragma unroll
    for (int i = 0; i < 5; i++) { d[i] = g_deg[base + i]; s += d[i]; }
    int tot = s;
#pragma unroll
    for (int off = 1; off < 32; off <<= 1) {
        int v = __shfl_up_sync(0xffffffffu, s, off);
        if (lane >= off) s += v;
    }
    __shared__ int ws[32];
    if (lane == 31) ws[wd] = s;
    __syncthreads();
    if (wd == 0) {
        int v = ws[lane];
#pragma unroll
        for (int off = 1; off < 32; off <<= 1) {
            int u = __shfl_up_sync(0xffffffffu, v, off);
            if (lane >= off) v += u;
        }
        ws[lane] = v;
    }
    __syncthreads();
    int pre = s - tot + (wd > 0 ? ws[wd - 1] : 0);
#pragma unroll
    for (int i = 0; i < 5; i++) {
        g_row[base + i]  = pre;
        pre += d[i];
        g_dinv[base + i] = d[i] > 0 ? rsqrtf((float)d[i]) : 0.f;
    }
}

// ---------------- stage 4: CSR fill (4 edges/thread) ----------------
__global__ void k_csr(const int* __restrict__ ei) {
    int t = blockIdx.x * 256 + threadIdx.x;            // 160 blocks
    const int4* s4 = (const int4*)ei;
    const int4* d4 = (const int4*)(ei + N_EDGES);
    int4 s = s4[t];
    int4 d = d4[t];
    int p0 = atomicAdd(&g_cur[d.x], 1);
    int p1 = atomicAdd(&g_cur[d.y], 1);
    int p2 = atomicAdd(&g_cur[d.z], 1);
    int p3 = atomicAdd(&g_cur[d.w], 1);
    g_csr[g_row[d.x] + p0] = s.x;
    g_csr[g_row[d.y] + p1] = s.y;
    g_csr[g_row[d.z] + p2] = s.z;
    g_csr[g_row[d.w] + p3] = s.w;
}

// ---------------- stage 5: gather-aggregate + bias + relu (640 blocks) -------
__global__ void k_gather(const float* __restrict__ bg) {
    int node = blockIdx.x * 8 + (threadIdx.x >> 5);
    int lane = threadIdx.x & 31;
    int start = g_row[node];
    int cnt   = g_deg[node];
    float dd  = g_dinv[node];
    float4 a0 = {0,0,0,0}, a1 = {0,0,0,0}, a2 = {0,0,0,0}, a3 = {0,0,0,0};
    const float4* h4 = (const float4*)g_h;
    int j = 0;
    for (; j + 4 <= cnt; j += 4) {
        int s0 = g_csr[start + j],     s1 = g_csr[start + j + 1];
        int s2 = g_csr[start + j + 2], s3 = g_csr[start + j + 3];
        float w0 = g_dinv[s0], w1 = g_dinv[s1], w2 = g_dinv[s2], w3 = g_dinv[s3];
        float4 v0 = h4[s0 * 32 + lane], v1 = h4[s1 * 32 + lane];
        float4 v2 = h4[s2 * 32 + lane], v3 = h4[s3 * 32 + lane];
        a0.x += w0 * v0.x; a0.y += w0 * v0.y; a0.z += w0 * v0.z; a0.w += w0 * v0.w;
        a1.x += w1 * v1.x; a1.y += w1 * v1.y; a1.z += w1 * v1.z; a1.w += w1 * v1.w;
        a2.x += w2 * v2.x; a2.y += w2 * v2.y; a2.z += w2 * v2.z; a2.w += w2 * v2.w;
        a3.x += w3 * v3.x; a3.y += w3 * v3.y; a3.z += w3 * v3.z; a3.w += w3 * v3.w;
    }
    for (; j < cnt; j++) {
        int s0 = g_csr[start + j];
        float w0 = g_dinv[s0];
        float4 v0 = h4[s0 * 32 + lane];
        a0.x += w0 * v0.x; a0.y += w0 * v0.y; a0.z += w0 * v0.z; a0.w += w0 * v0.w;
    }
    float4 acc;
    acc.x = (a0.x + a1.x) + (a2.x + a3.x);
    acc.y = (a0.y + a1.y) + (a2.y + a3.y);
    acc.z = (a0.z + a1.z) + (a2.z + a3.z);
    acc.w = (a0.w + a1.w) + (a2.w + a3.w);
    float4 bv = ((const float4*)bg)[lane];
    acc.x = fmaxf(acc.x * dd + bv.x, 0.f);
    acc.y = fmaxf(acc.y * dd + bv.y, 0.f);
    acc.z = fmaxf(acc.z * dd + bv.z, 0.f);
    acc.w = fmaxf(acc.w * dd + bv.w, 0.f);
    ((float4*)g_z)[node * 32 + lane] = acc;
}

// ---------------- stage 6: per-graph outer product z z^T -> fp16 ------------
__global__ void k_outer() {
    __shared__ float Zs[NN][LAT + 1];
    int b = blockIdx.x, tid = threadIdx.x;
#pragma unroll
    for (int i = 0; i < 40; i++) {
        int idx = tid + i * 256;
        Zs[idx >> 7][idx & 127] = g_z[b * NN * LAT + idx];
    }
    __syncthreads();
    int rn = (tid >> 4) * 5;
    int rm = (tid & 15) * 5;
    float acc[5][5] = {};
    for (int l = 0; l < LAT; l++) {
        float a[5], bb[5];
#pragma unroll
        for (int i = 0; i < 5; i++) a[i]  = Zs[rn + i][l];
#pragma unroll
        for (int j = 0; j < 5; j++) bb[j] = Zs[rm + j][l];
#pragma unroll
        for (int i = 0; i < 5; i++)
#pragma unroll
            for (int j = 0; j < 5; j++) acc[i][j] += a[i] * bb[j];
    }
#pragma unroll
    for (int i = 0; i < 5; i++)
#pragma unroll
        for (int j = 0; j < 5; j++)
            g_z2h[b * N2 + (rn + i) * NN + (rm + j)] = __float2half(acc[i][j]);
}

// ======================= fp16 mma.sync GEMM (fp32 acc) =======================
__device__ __forceinline__ uint32_t sptr(const void* p) {
    return (uint32_t)__cvta_generic_to_shared(p);
}
__device__ __forceinline__ void cp16(uint32_t s, const void* g) {
    asm volatile("cp.async.cg.shared.global [%0], [%1], 16;" :: "r"(s), "l"(g));
}
__device__ __forceinline__ void mma16(float* c, const uint32_t* a, const uint32_t* b) {
    asm volatile(
        "mma.sync.aligned.m16n8k16.row.col.f32.f16.f16.f32 "
        "{%0,%1,%2,%3}, {%4,%5,%6,%7}, {%8,%9}, {%0,%1,%2,%3};"
        : "+f"(c[0]), "+f"(c[1]), "+f"(c[2]), "+f"(c[3])
        : "r"(a[0]), "r"(a[1]), "r"(a[2]), "r"(a[3]), "r"(b[0]), "r"(b[1]));
}
__device__ __forceinline__ uint32_t packh2(float lo, float hi) {
    __half2 h = __floats2half2_rn(lo, hi);
    return *(uint32_t*)&h;
}

// smem (4 stages), K_CHUNK = 16:
//   A: fp16, 64 rows x 40 halves (16 used + 24 pad) = 80B/row -> 5120B/stage
//   B: fp32, 16 rows x 260 floats (256 used + 4 pad) = 1040B/row -> 16640B/stage
#define A_ROWH  40
#define A_STGB  5120
#define B_ROWF  260
#define B_STGB  16640
#define B_OFFB  (4 * A_STGB)
#define MM_SMEM (4 * A_STGB + 4 * B_STGB)   // 87040 bytes

// CTA: 64(M) x 256(N), 8 warps (2x4), warp tile 32x64, K_CHUNK=16, 4 stages.
template<int MODE>
__global__ __launch_bounds__(256, 2) void k_mm(const float* __restrict__ W) {
    constexpr int K    = (MODE == 1) ? N2 : H1;
    constexpr int NOUT = (MODE == 1) ? H1 : N2;
    constexpr int NSPL = (MODE == 1) ? 6 : 12;   // 300 CTAs each (R7-proven)
    const __half* A = (MODE == 1) ? g_z2h : g_z3h;
    float* outp     = (MODE == 1) ? g_p1[blockIdx.y] : g_p2[blockIdx.y];

    extern __shared__ char smc[];
    char* Ab = smc;
    char* Bb = smc + B_OFFB;

    const int tid = threadIdx.x;
    const int n0  = blockIdx.x * 256;
    const int sp  = blockIdx.y;

    constexpr int TOT = K / 16;
    constexpr int per = TOT / NSPL, rem = TOT % NSPL;
    const int ks0 = sp * per + min(sp, rem);
    const int cnt = per + (sp < rem ? 1 : 0);

    const int lane = tid & 31, wp = tid >> 5;
    const int wm = wp >> 2, wn = wp & 3;      // 2 x 4 warp grid
    const int gq = lane >> 2, tq = lane & 3;

    // A staging: 64 rows x 2 16B-chunks = 128 cp16 (threads 0-127)
    const int a_r = tid >> 1, a_ch = tid & 1;
    const uint32_t a_base = sptr(Ab);
    const uint32_t b_base = sptr(Bb);

    auto issue = [&](int st, int ki) {
        int kk = (ks0 + ki) * 16;
        if (tid < 128)
            cp16(a_base + (uint32_t)(st * A_STGB + a_r * 80 + a_ch * 16),
                 A + (size_t)a_r * K + kk + a_ch * 8);
#pragma unroll
        for (int q = 0; q < 4; q++) {
            int id = tid + q * 256;
            int r  = id >> 6, c4 = (id & 63) * 4;
            cp16(b_base + (uint32_t)(st * B_STGB + (r * B_ROWF + c4) * 4),
                 W + (size_t)(kk + r) * NOUT + n0 + c4);
        }
    };

    float C[2][8][4] = {};

    issue(0, 0); asm volatile("cp.async.commit_group;");
    if (cnt > 1) issue(1, 1);
    asm volatile("cp.async.commit_group;");
    if (cnt > 2) issue(2, 2);
    asm volatile("cp.async.commit_group;");

    for (int i = 0; i < cnt; i++) {
        asm volatile("cp.async.wait_group 2;");
        __syncthreads();
        const int st = i & 3;
        const char*  ab = Ab + st * A_STGB;
        const float* bs = (const float*)(Bb + st * B_STGB);

        uint32_t a[2][4], b[8][2];
#pragma unroll
        for (int mi = 0; mi < 2; mi++) {
            int r = wm * 32 + mi * 16 + gq;
            a[mi][0] = *(const uint32_t*)(ab + r * 80 + tq * 4);            // k 2tq,2tq+1
            a[mi][1] = *(const uint32_t*)(ab + (r + 8) * 80 + tq * 4);
            a[mi][2] = *(const uint32_t*)(ab + r * 80 + 16 + tq * 4);       // k +8
            a[mi][3] = *(const uint32_t*)(ab + (r + 8) * 80 + 16 + tq * 4);
        }
#pragma unroll
        for (int ni = 0; ni < 8; ni++) {
            int c = wn * 64 + ni * 8 + gq;
            b[ni][0] = packh2(bs[(2 * tq) * B_ROWF + c],     bs[(2 * tq + 1) * B_ROWF + c]);
            b[ni][1] = packh2(bs[(2 * tq + 8) * B_ROWF + c], bs[(2 * tq + 9) * B_ROWF + c]);
        }
#pragma unroll
        for (int mi = 0; mi < 2; mi++)
#pragma unroll
            for (int ni = 0; ni < 8; ni++)
                mma16(C[mi][ni], a[mi], b[ni]);

        int nx = i + 3;
        if (nx < cnt) issue(nx & 3, nx);
        asm volatile("cp.async.commit_group;");
    }

    // write split-K partials (summed in epilogue)
#pragma unroll
    for (int mi = 0; mi < 2; mi++)
#pragma unroll
        for (int ni = 0; ni < 8; ni++) {
            int r = wm * 32 + mi * 16 + gq;
            int c = n0 + wn * 64 + ni * 8 + 2 * tq;
            *(float2*)&outp[(size_t)r * NOUT + c]       = make_float2(C[mi][ni][0], C[mi][ni][1]);
            *(float2*)&outp[(size_t)(r + 8) * NOUT + c] = make_float2(C[mi][ni][2], C[mi][ni][3]);
        }
}

// ---------------- epilogues ----------------
__global__ void k_epi1(const float* __restrict__ b1) {
    int g = blockIdx.x * 256 + threadIdx.x;      // float4 index
    int e = g * 4;
    float4 v = *(const float4*)&g_p1[0][e];
#pragma unroll
    for (int s = 1; s < 6; s++) {
        float4 p = *(const float4*)&g_p1[s][e];
        v.x += p.x; v.y += p.y; v.z += p.z; v.w += p.w;
    }
    float4 bb = *(const float4*)&b1[e % H1];
    v.x = fmaxf(v.x + bb.x, 0.f); v.y = fmaxf(v.y + bb.y, 0.f);
    v.z = fmaxf(v.z + bb.z, 0.f); v.w = fmaxf(v.w + bb.w, 0.f);
    __half2 h01 = __floats2half2_rn(v.x, v.y);
    __half2 h23 = __floats2half2_rn(v.z, v.w);
    uint2 pk = make_uint2(*(uint32_t*)&h01, *(uint32_t*)&h23);
    *(uint2*)&g_z3h[e] = pk;
}
__global__ void k_epi2(const float* __restrict__ b2, float* __restrict__ out) {
    int g = blockIdx.x * 256 + threadIdx.x;
    int e = g * 4;
    float4 v = *(const float4*)&g_p2[0][e];
#pragma unroll
    for (int s = 1; s < 12; s++) {
        float4 p = *(const float4*)&g_p2[s][e];
        v.x += p.x; v.y += p.y; v.z += p.z; v.w += p.w;
    }
    float4 bb = *(const float4*)&b2[e % N2];
    v.x += bb.x; v.y += bb.y; v.z += bb.z; v.w += bb.w;
    float4 o;
    o.x = 1.f / (1.f + __expf(-v.x));
    o.y = 1.f / (1.f + __expf(-v.y));
    o.z = 1.f / (1.f + __expf(-v.z));
    o.w = 1.f / (1.f + __expf(-v.w));
    *(float4*)&out[e] = o;
}

// ---------------- launch ----------------
extern "C" void kernel_launch(void* const* d_in, const int* in_sizes, int n_in,
                              void* d_out, int out_size) {
    const float* x  = (const float*)d_in[0];
    const int*   ei = (const int*)  d_in[1];
    const float* Wg = (const float*)d_in[2];
    const float* bg = (const float*)d_in[3];
    const float* W1 = (const float*)d_in[4];
    const float* b1 = (const float*)d_in[5];
    const float* W2 = (const float*)d_in[6];
    const float* b2 = (const float*)d_in[7];
    float* out = (float*)d_out;

    static bool attr_done = false;
    if (!attr_done) {
        cudaFuncSetAttribute(k_mm<1>, cudaFuncAttributeMaxDynamicSharedMemorySize, MM_SMEM);
        cudaFuncSetAttribute(k_mm<2>, cudaFuncAttributeMaxDynamicSharedMemorySize, MM_SMEM);
        attr_done = true;
    }

    k_prep  <<<180, 256>>>(x, Wg);
    k_deg   <<<160, 256>>>(ei);
    k_scan  <<<1, 1024>>>();
    k_csr   <<<160, 256>>>(ei);
    k_gather<<<640, 256>>>(bg);
    k_outer <<<64, 256>>>();
    k_mm<1> <<<dim3(50, 6),  256, MM_SMEM>>>(W1);   // 300 CTAs @ 2/SM (R7-proven)
    k_epi1  <<<NG * H1 / 1024, 256>>>(b1);
    k_mm<2> <<<dim3(25, 12), 256, MM_SMEM>>>(W2);   // 300 CTAs @ 2/SM
    k_epi2  <<<NG * N2 / 1024, 256>>>(b2, out);
}

// round 14
// speedup vs baseline: 1.3264x; 1.0905x over previous
#include <cuda_runtime.h>
#include <cuda_fp16.h>
#include <cstdint>

#define N_NODES 5120
#define N_EDGES 163840
#define TBLD    256
#define LAT     128
#define NG      64
#define NN      80
#define N2      6400
#define H1      12800
#define BKT     96          // bucket capacity per node (max in-degree ~57)

// ---------------- scratch (no allocs allowed) ----------------
__device__ __align__(128) float  g_h  [N_NODES * LAT];
__device__ __align__(128) float  g_z  [N_NODES * LAT];
__device__ __align__(128) __half g_z2h[NG * N2];     // GEMM1 A (fp16)
__device__ __align__(128) __half g_z3h[NG * H1];     // GEMM2 A (fp16)
__device__ __align__(128) float  g_p1[6][NG * H1];   // GEMM1 split-K partials
__device__ __align__(128) float  g_p2[12][NG * N2];  // GEMM2 split-K partials
__device__ int g_cur [N_NODES];
__device__ int g_csrB[N_NODES * BKT];

// ---------------- stage 1: clear counters + h = x @ Wg (merged) --------------
__global__ void k_prep(const float* __restrict__ x, const float* __restrict__ Wg) {
    if (blockIdx.x >= 160) {   // clear part
        int i = (blockIdx.x - 160) * 256 + threadIdx.x;
        if (i < N_NODES) g_cur[i] = 0;
        return;
    }
    __shared__ float Xs[32][33];
    __shared__ float Ws[32][128];
    int tid = threadIdx.x;
    int m0  = blockIdx.x * 32;
    int tm  = (tid >> 5) * 4;
    int tn  = (tid & 31) * 4;
    float acc[4][4] = {};
    for (int k0 = 0; k0 < TBLD; k0 += 32) {
        int r = tid >> 3, c = (tid & 7) * 4;
        float4 xv = *(const float4*)&x[(m0 + r) * TBLD + k0 + c];
        Xs[r][c] = xv.x; Xs[r][c + 1] = xv.y; Xs[r][c + 2] = xv.z; Xs[r][c + 3] = xv.w;
#pragma unroll
        for (int i = 0; i < 4; i++) {
            int idx = tid + i * 256;
            int wr = idx >> 5, wc = (idx & 31) * 4;
            *(float4*)&Ws[wr][wc] = *(const float4*)&Wg[(k0 + wr) * LAT + wc];
        }
        __syncthreads();
#pragma unroll
        for (int kk = 0; kk < 32; kk++) {
            float a0 = Xs[tm][kk], a1 = Xs[tm + 1][kk], a2 = Xs[tm + 2][kk], a3 = Xs[tm + 3][kk];
            float4 bv = *(float4*)&Ws[kk][tn];
            acc[0][0] += a0 * bv.x; acc[0][1] += a0 * bv.y; acc[0][2] += a0 * bv.z; acc[0][3] += a0 * bv.w;
            acc[1][0] += a1 * bv.x; acc[1][1] += a1 * bv.y; acc[1][2] += a1 * bv.z; acc[1][3] += a1 * bv.w;
            acc[2][0] += a2 * bv.x; acc[2][1] += a2 * bv.y; acc[2][2] += a2 * bv.z; acc[2][3] += a2 * bv.w;
            acc[3][0] += a3 * bv.x; acc[3][1] += a3 * bv.y; acc[3][2] += a3 * bv.z; acc[3][3] += a3 * bv.w;
        }
        __syncthreads();
    }
#pragma unroll
    for (int i = 0; i < 4; i++) {
        float4 v = make_float4(acc[i][0], acc[i][1], acc[i][2], acc[i][3]);
        *(float4*)&g_h[(m0 + tm + i) * LAT + tn] = v;
    }
}

// ---------------- stage 2: bucket-CSR build (replaces deg+scan+csr) ----------
__global__ void k_csrB(const int* __restrict__ ei) {
    int t = blockIdx.x * 256 + threadIdx.x;            // 160 blocks
    const int4* s4 = (const int4*)ei;
    const int4* d4 = (const int4*)(ei + N_EDGES);
    int4 s = s4[t];
    int4 d = d4[t];
    int p0 = atomicAdd(&g_cur[d.x], 1);
    int p1 = atomicAdd(&g_cur[d.y], 1);
    int p2 = atomicAdd(&g_cur[d.z], 1);
    int p3 = atomicAdd(&g_cur[d.w], 1);
    g_csrB[d.x * BKT + p0] = s.x;
    g_csrB[d.y * BKT + p1] = s.y;
    g_csrB[d.z * BKT + p2] = s.z;
    g_csrB[d.w * BKT + p3] = s.w;
}

// ---------------- stage 3: gather-aggregate + bias + relu --------------------
// dinv factors computed on the fly from bucket counts.
__global__ void k_gather(const float* __restrict__ bg) {
    int node = blockIdx.x * 8 + (threadIdx.x >> 5);
    int lane = threadIdx.x & 31;
    int cnt  = g_cur[node];
    float dd = cnt > 0 ? rsqrtf((float)cnt) : 0.f;
    int base = node * BKT;
    float4 a0 = {0,0,0,0}, a1 = {0,0,0,0}, a2 = {0,0,0,0}, a3 = {0,0,0,0};
    const float4* h4 = (const float4*)g_h;
    int j = 0;
    for (; j + 4 <= cnt; j += 4) {
        int s0 = g_csrB[base + j],     s1 = g_csrB[base + j + 1];
        int s2 = g_csrB[base + j + 2], s3 = g_csrB[base + j + 3];
        int c0 = g_cur[s0], c1 = g_cur[s1], c2 = g_cur[s2], c3 = g_cur[s3];
        float w0 = c0 > 0 ? rsqrtf((float)c0) : 0.f;
        float w1 = c1 > 0 ? rsqrtf((float)c1) : 0.f;
        float w2 = c2 > 0 ? rsqrtf((float)c2) : 0.f;
        float w3 = c3 > 0 ? rsqrtf((float)c3) : 0.f;
        float4 v0 = h4[s0 * 32 + lane], v1 = h4[s1 * 32 + lane];
        float4 v2 = h4[s2 * 32 + lane], v3 = h4[s3 * 32 + lane];
        a0.x += w0 * v0.x; a0.y += w0 * v0.y; a0.z += w0 * v0.z; a0.w += w0 * v0.w;
        a1.x += w1 * v1.x; a1.y += w1 * v1.y; a1.z += w1 * v1.z; a1.w += w1 * v1.w;
        a2.x += w2 * v2.x; a2.y += w2 * v2.y; a2.z += w2 * v2.z; a2.w += w2 * v2.w;
        a3.x += w3 * v3.x; a3.y += w3 * v3.y; a3.z += w3 * v3.z; a3.w += w3 * v3.w;
    }
    for (; j < cnt; j++) {
        int s0 = g_csrB[base + j];
        int c0 = g_cur[s0];
        float w0 = c0 > 0 ? rsqrtf((float)c0) : 0.f;
        float4 v0 = h4[s0 * 32 + lane];
        a0.x += w0 * v0.x; a0.y += w0 * v0.y; a0.z += w0 * v0.z; a0.w += w0 * v0.w;
    }
    float4 acc;
    acc.x = (a0.x + a1.x) + (a2.x + a3.x);
    acc.y = (a0.y + a1.y) + (a2.y + a3.y);
    acc.z = (a0.z + a1.z) + (a2.z + a3.z);
    acc.w = (a0.w + a1.w) + (a2.w + a3.w);
    float4 bv = ((const float4*)bg)[lane];
    acc.x = fmaxf(acc.x * dd + bv.x, 0.f);
    acc.y = fmaxf(acc.y * dd + bv.y, 0.f);
    acc.z = fmaxf(acc.z * dd + bv.z, 0.f);
    acc.w = fmaxf(acc.w * dd + bv.w, 0.f);
    ((float4*)g_z)[node * 32 + lane] = acc;
}

// ------- stage 4: per-graph outer product z z^T -> fp16 (2 blocks/graph) -----
__global__ __launch_bounds__(128) void k_outer() {
    __shared__ float Zs[NN][LAT + 1];
    int b = blockIdx.x >> 1, half = blockIdx.x & 1;
    int tid = threadIdx.x;                  // 128 threads
#pragma unroll
    for (int i = 0; i < 80; i++) {
        int idx = tid + i * 128;
        Zs[idx >> 7][idx & 127] = g_z[b * NN * LAT + idx];
    }
    __syncthreads();
    int rn = (tid >> 3) * 5;                // 16 positions: rows 0..75
    int rm = half * 40 + (tid & 7) * 5;     // 8 positions per half
    float acc[5][5] = {};
    for (int l = 0; l < LAT; l++) {
        float a[5], bb[5];
#pragma unroll
        for (int i = 0; i < 5; i++) a[i]  = Zs[rn + i][l];
#pragma unroll
        for (int j = 0; j < 5; j++) bb[j] = Zs[rm + j][l];
#pragma unroll
        for (int i = 0; i < 5; i++)
#pragma unroll
            for (int j = 0; j < 5; j++) acc[i][j] += a[i] * bb[j];
    }
#pragma unroll
    for (int i = 0; i < 5; i++)
#pragma unroll
        for (int j = 0; j < 5; j++)
            g_z2h[b * N2 + (rn + i) * NN + (rm + j)] = __float2half(acc[i][j]);
}

// ======================= fp16 mma.sync GEMM (fp32 acc) =======================
__device__ __forceinline__ uint32_t sptr(const void* p) {
    return (uint32_t)__cvta_generic_to_shared(p);
}
__device__ __forceinline__ void cp16(uint32_t s, const void* g) {
    asm volatile("cp.async.cg.shared.global [%0], [%1], 16;" :: "r"(s), "l"(g));
}
__device__ __forceinline__ void mma16(float* c, const uint32_t* a, const uint32_t* b) {
    asm volatile(
        "mma.sync.aligned.m16n8k16.row.col.f32.f16.f16.f32 "
        "{%0,%1,%2,%3}, {%4,%5,%6,%7}, {%8,%9}, {%0,%1,%2,%3};"
        : "+f"(c[0]), "+f"(c[1]), "+f"(c[2]), "+f"(c[3])
        : "r"(a[0]), "r"(a[1]), "r"(a[2]), "r"(a[3]), "r"(b[0]), "r"(b[1]));
}
__device__ __forceinline__ uint32_t packh2(float lo, float hi) {
    __half2 h = __floats2half2_rn(lo, hi);
    return *(uint32_t*)&h;
}

// smem (4 stages), K_CHUNK = 16:
//   A: fp16, 64 rows x 40 halves (16 used + 24 pad) = 80B/row -> 5120B/stage
//   B: fp32, 16 rows x 260 floats (256 used + 4 pad) = 1040B/row -> 16640B/stage
#define A_STGB  5120
#define B_ROWF  260
#define B_STGB  16640
#define B_OFFB  (4 * A_STGB)
#define MM_SMEM (4 * A_STGB + 4 * B_STGB)   // 87040 bytes

// CTA: 64(M) x 256(N), 8 warps (2x4), warp tile 32x64, K_CHUNK=16, 4 stages.
template<int MODE>
__global__ __launch_bounds__(256, 2) void k_mm(const float* __restrict__ W) {
    constexpr int K    = (MODE == 1) ? N2 : H1;
    constexpr int NOUT = (MODE == 1) ? H1 : N2;
    constexpr int NSPL = (MODE == 1) ? 6 : 12;   // 300 CTAs each (proven)
    const __half* A = (MODE == 1) ? g_z2h : g_z3h;
    float* outp     = (MODE == 1) ? g_p1[blockIdx.y] : g_p2[blockIdx.y];

    extern __shared__ char smc[];
    char* Ab = smc;
    char* Bb = smc + B_OFFB;

    const int tid = threadIdx.x;
    const int n0  = blockIdx.x * 256;
    const int sp  = blockIdx.y;

    constexpr int TOT = K / 16;
    constexpr int per = TOT / NSPL, rem = TOT % NSPL;
    const int ks0 = sp * per + min(sp, rem);
    const int cnt = per + (sp < rem ? 1 : 0);

    const int lane = tid & 31, wp = tid >> 5;
    const int wm = wp >> 2, wn = wp & 3;      // 2 x 4 warp grid
    const int gq = lane >> 2, tq = lane & 3;

    const int a_r = tid >> 1, a_ch = tid & 1;
    const uint32_t a_base = sptr(Ab);
    const uint32_t b_base = sptr(Bb);

    auto issue = [&](int st, int ki) {
        int kk = (ks0 + ki) * 16;
        if (tid < 128)
            cp16(a_base + (uint32_t)(st * A_STGB + a_r * 80 + a_ch * 16),
                 A + (size_t)a_r * K + kk + a_ch * 8);
#pragma unroll
        for (int q = 0; q < 4; q++) {
            int id = tid + q * 256;
            int r  = id >> 6, c4 = (id & 63) * 4;
            cp16(b_base + (uint32_t)(st * B_STGB + (r * B_ROWF + c4) * 4),
                 W + (size_t)(kk + r) * NOUT + n0 + c4);
        }
    };

    float C[2][8][4] = {};

    issue(0, 0); asm volatile("cp.async.commit_group;");
    if (cnt > 1) issue(1, 1);
    asm volatile("cp.async.commit_group;");
    if (cnt > 2) issue(2, 2);
    asm volatile("cp.async.commit_group;");

    for (int i = 0; i < cnt; i++) {
        asm volatile("cp.async.wait_group 2;");
        __syncthreads();
        const int st = i & 3;
        const char*  ab = Ab + st * A_STGB;
        const float* bs = (const float*)(Bb + st * B_STGB);

        uint32_t a[2][4], b[8][2];
#pragma unroll
        for (int mi = 0; mi < 2; mi++) {
            int r = wm * 32 + mi * 16 + gq;
            a[mi][0] = *(const uint32_t*)(ab + r * 80 + tq * 4);
            a[mi][1] = *(const uint32_t*)(ab + (r + 8) * 80 + tq * 4);
            a[mi][2] = *(const uint32_t*)(ab + r * 80 + 16 + tq * 4);
            a[mi][3] = *(const uint32_t*)(ab + (r + 8) * 80 + 16 + tq * 4);
        }
#pragma unroll
        for (int ni = 0; ni < 8; ni++) {
            int c = wn * 64 + ni * 8 + gq;
            b[ni][0] = packh2(bs[(2 * tq) * B_ROWF + c],     bs[(2 * tq + 1) * B_ROWF + c]);
            b[ni][1] = packh2(bs[(2 * tq + 8) * B_ROWF + c], bs[(2 * tq + 9) * B_ROWF + c]);
        }
#pragma unroll
        for (int mi = 0; mi < 2; mi++)
#pragma unroll
            for (int ni = 0; ni < 8; ni++)
                mma16(C[mi][ni], a[mi], b[ni]);

        int nx = i + 3;
        if (nx < cnt) issue(nx & 3, nx);
        asm volatile("cp.async.commit_group;");
    }

    // write split-K partials (summed in epilogue)
#pragma unroll
    for (int mi = 0; mi < 2; mi++)
#pragma unroll
        for (int ni = 0; ni < 8; ni++) {
            int r = wm * 32 + mi * 16 + gq;
            int c = n0 + wn * 64 + ni * 8 + 2 * tq;
            *(float2*)&outp[(size_t)r * NOUT + c]       = make_float2(C[mi][ni][0], C[mi][ni][1]);
            *(float2*)&outp[(size_t)(r + 8) * NOUT + c] = make_float2(C[mi][ni][2], C[mi][ni][3]);
        }
}

// ---------------- epilogues ----------------
__global__ void k_epi1(const float* __restrict__ b1) {
    int g = blockIdx.x * 256 + threadIdx.x;      // float4 index
    int e = g * 4;
    float4 v = *(const float4*)&g_p1[0][e];
#pragma unroll
    for (int s = 1; s < 6; s++) {
        float4 p = *(const float4*)&g_p1[s][e];
        v.x += p.x; v.y += p.y; v.z += p.z; v.w += p.w;
    }
    float4 bb = *(const float4*)&b1[e % H1];
    v.x = fmaxf(v.x + bb.x, 0.f); v.y = fmaxf(v.y + bb.y, 0.f);
    v.z = fmaxf(v.z + bb.z, 0.f); v.w = fmaxf(v.w + bb.w, 0.f);
    __half2 h01 = __floats2half2_rn(v.x, v.y);
    __half2 h23 = __floats2half2_rn(v.z, v.w);
    uint2 pk = make_uint2(*(uint32_t*)&h01, *(uint32_t*)&h23);
    *(uint2*)&g_z3h[e] = pk;
}
__global__ void k_epi2(const float* __restrict__ b2, float* __restrict__ out) {
    int g = blockIdx.x * 256 + threadIdx.x;
    int e = g * 4;
    float4 v = *(const float4*)&g_p2[0][e];
#pragma unroll
    for (int s = 1; s < 12; s++) {
        float4 p = *(const float4*)&g_p2[s][e];
        v.x += p.x; v.y += p.y; v.z += p.z; v.w += p.w;
    }
    float4 bb = *(const float4*)&b2[e % N2];
    v.x += bb.x; v.y += bb.y; v.z += bb.z; v.w += bb.w;
    float4 o;
    o.x = 1.f / (1.f + __expf(-v.x));
    o.y = 1.f / (1.f + __expf(-v.y));
    o.z = 1.f / (1.f + __expf(-v.z));
    o.w = 1.f / (1.f + __expf(-v.w));
    *(float4*)&out[e] = o;
}

// ---------------- launch ----------------
extern "C" void kernel_launch(void* const* d_in, const int* in_sizes, int n_in,
                              void* d_out, int out_size) {
    const float* x  = (const float*)d_in[0];
    const int*   ei = (const int*)  d_in[1];
    const float* Wg = (const float*)d_in[2];
    const float* bg = (const float*)d_in[3];
    const float* W1 = (const float*)d_in[4];
    const float* b1 = (const float*)d_in[5];
    const float* W2 = (const float*)d_in[6];
    const float* b2 = (const float*)d_in[7];
    float* out = (float*)d_out;

    static bool attr_done = false;
    if (!attr_done) {
        cudaFuncSetAttribute(k_mm<1>, cudaFuncAttributeMaxDynamicSharedMemorySize, MM_SMEM);
        cudaFuncSetAttribute(k_mm<2>, cudaFuncAttributeMaxDynamicSharedMemorySize, MM_SMEM);
        attr_done = true;
    }

    k_prep  <<<180, 256>>>(x, Wg);
    k_csrB  <<<160, 256>>>(ei);
    k_gather<<<640, 256>>>(bg);
    k_outer <<<128, 128>>>();
    k_mm<1> <<<dim3(50, 6),  256, MM_SMEM>>>(W1);   // 300 CTAs @ 2/SM
    k_epi1  <<<NG * H1 / 1024, 256>>>(b1);
    k_mm<2> <<<dim3(25, 12), 256, MM_SMEM>>>(W2);   // 300 CTAs @ 2/SM
    k_epi2  <<<NG * N2 / 1024, 256>>>(b2, out);
}

// round 15
// speedup vs baseline: 1.3591x; 1.0246x over previous
#include <cuda_runtime.h>
#include <cuda_fp16.h>
#include <cstdint>

#define N_NODES 5120
#define N_EDGES 163840
#define TBLD    256
#define LAT     128
#define NG      64
#define NN      80
#define N2      6400
#define H1      12800
#define BKT     96          // bucket capacity per node (max in-degree ~57)

// ---------------- scratch (no allocs allowed) ----------------
__device__ __align__(128) float  g_h  [N_NODES * LAT];
__device__ __align__(128) float  g_z  [N_NODES * LAT];
__device__ __align__(128) __half g_z2h[NG * N2];     // GEMM1 A (fp16)
__device__ __align__(128) __half g_z3h[NG * H1];     // GEMM2 A (fp16)
__device__ __align__(128) float  g_p1[6][NG * H1];   // GEMM1 split-K partials
__device__ __align__(128) float  g_p2[12][NG * N2];  // GEMM2 split-K partials
__device__ int g_cur [N_NODES];                      // zero at entry (reset by k_epi2)
__device__ int g_csrB[N_NODES * BKT];

// ------- stage 1: h = x @ Wg (blocks 0-159)  ||  bucket-CSR (blocks 160-319) --
// g_cur is guaranteed zero at kernel entry (module-load init on call 1,
// k_epi2 resets it at the end of every call), so both halves are independent.
__global__ void k_prep(const float* __restrict__ x, const float* __restrict__ Wg,
                       const int* __restrict__ ei) {
    if (blockIdx.x >= 160) {   // CSR bucket build: atomic-bound, overlaps h-GEMM
        int t = (blockIdx.x - 160) * 256 + threadIdx.x;
        const int4* s4 = (const int4*)ei;
        const int4* d4 = (const int4*)(ei + N_EDGES);
        int4 s = s4[t];
        int4 d = d4[t];
        int p0 = atomicAdd(&g_cur[d.x], 1);
        int p1 = atomicAdd(&g_cur[d.y], 1);
        int p2 = atomicAdd(&g_cur[d.z], 1);
        int p3 = atomicAdd(&g_cur[d.w], 1);
        g_csrB[d.x * BKT + p0] = s.x;
        g_csrB[d.y * BKT + p1] = s.y;
        g_csrB[d.z * BKT + p2] = s.z;
        g_csrB[d.w * BKT + p3] = s.w;
        return;
    }
    __shared__ float Xs[32][33];
    __shared__ float Ws[32][128];
    int tid = threadIdx.x;
    int m0  = blockIdx.x * 32;
    int tm  = (tid >> 5) * 4;
    int tn  = (tid & 31) * 4;
    float acc[4][4] = {};
    for (int k0 = 0; k0 < TBLD; k0 += 32) {
        int r = tid >> 3, c = (tid & 7) * 4;
        float4 xv = *(const float4*)&x[(m0 + r) * TBLD + k0 + c];
        Xs[r][c] = xv.x; Xs[r][c + 1] = xv.y; Xs[r][c + 2] = xv.z; Xs[r][c + 3] = xv.w;
#pragma unroll
        for (int i = 0; i < 4; i++) {
            int idx = tid + i * 256;
            int wr = idx >> 5, wc = (idx & 31) * 4;
            *(float4*)&Ws[wr][wc] = *(const float4*)&Wg[(k0 + wr) * LAT + wc];
        }
        __syncthreads();
#pragma unroll
        for (int kk = 0; kk < 32; kk++) {
            float a0 = Xs[tm][kk], a1 = Xs[tm + 1][kk], a2 = Xs[tm + 2][kk], a3 = Xs[tm + 3][kk];
            float4 bv = *(float4*)&Ws[kk][tn];
            acc[0][0] += a0 * bv.x; acc[0][1] += a0 * bv.y; acc[0][2] += a0 * bv.z; acc[0][3] += a0 * bv.w;
            acc[1][0] += a1 * bv.x; acc[1][1] += a1 * bv.y; acc[1][2] += a1 * bv.z; acc[1][3] += a1 * bv.w;
            acc[2][0] += a2 * bv.x; acc[2][1] += a2 * bv.y; acc[2][2] += a2 * bv.z; acc[2][3] += a2 * bv.w;
            acc[3][0] += a3 * bv.x; acc[3][1] += a3 * bv.y; acc[3][2] += a3 * bv.z; acc[3][3] += a3 * bv.w;
        }
        __syncthreads();
    }
#pragma unroll
    for (int i = 0; i < 4; i++) {
        float4 v = make_float4(acc[i][0], acc[i][1], acc[i][2], acc[i][3]);
        *(float4*)&g_h[(m0 + tm + i) * LAT + tn] = v;
    }
}

// ---------------- stage 2: gather-aggregate + bias + relu --------------------
__global__ void k_gather(const float* __restrict__ bg) {
    int node = blockIdx.x * 8 + (threadIdx.x >> 5);
    int lane = threadIdx.x & 31;
    int cnt  = g_cur[node];
    float dd = cnt > 0 ? rsqrtf((float)cnt) : 0.f;
    int base = node * BKT;
    float4 a0 = {0,0,0,0}, a1 = {0,0,0,0}, a2 = {0,0,0,0}, a3 = {0,0,0,0};
    const float4* h4 = (const float4*)g_h;
    int j = 0;
    for (; j + 4 <= cnt; j += 4) {
        int s0 = g_csrB[base + j],     s1 = g_csrB[base + j + 1];
        int s2 = g_csrB[base + j + 2], s3 = g_csrB[base + j + 3];
        int c0 = g_cur[s0], c1 = g_cur[s1], c2 = g_cur[s2], c3 = g_cur[s3];
        float w0 = c0 > 0 ? rsqrtf((float)c0) : 0.f;
        float w1 = c1 > 0 ? rsqrtf((float)c1) : 0.f;
        float w2 = c2 > 0 ? rsqrtf((float)c2) : 0.f;
        float w3 = c3 > 0 ? rsqrtf((float)c3) : 0.f;
        float4 v0 = h4[s0 * 32 + lane], v1 = h4[s1 * 32 + lane];
        float4 v2 = h4[s2 * 32 + lane], v3 = h4[s3 * 32 + lane];
        a0.x += w0 * v0.x; a0.y += w0 * v0.y; a0.z += w0 * v0.z; a0.w += w0 * v0.w;
        a1.x += w1 * v1.x; a1.y += w1 * v1.y; a1.z += w1 * v1.z; a1.w += w1 * v1.w;
        a2.x += w2 * v2.x; a2.y += w2 * v2.y; a2.z += w2 * v2.z; a2.w += w2 * v2.w;
        a3.x += w3 * v3.x; a3.y += w3 * v3.y; a3.z += w3 * v3.z; a3.w += w3 * v3.w;
    }
    for (; j < cnt; j++) {
        int s0 = g_csrB[base + j];
        int c0 = g_cur[s0];
        float w0 = c0 > 0 ? rsqrtf((float)c0) : 0.f;
        float4 v0 = h4[s0 * 32 + lane];
        a0.x += w0 * v0.x; a0.y += w0 * v0.y; a0.z += w0 * v0.z; a0.w += w0 * v0.w;
    }
    float4 acc;
    acc.x = (a0.x + a1.x) + (a2.x + a3.x);
    acc.y = (a0.y + a1.y) + (a2.y + a3.y);
    acc.z = (a0.z + a1.z) + (a2.z + a3.z);
    acc.w = (a0.w + a1.w) + (a2.w + a3.w);
    float4 bv = ((const float4*)bg)[lane];
    acc.x = fmaxf(acc.x * dd + bv.x, 0.f);
    acc.y = fmaxf(acc.y * dd + bv.y, 0.f);
    acc.z = fmaxf(acc.z * dd + bv.z, 0.f);
    acc.w = fmaxf(acc.w * dd + bv.w, 0.f);
    ((float4*)g_z)[node * 32 + lane] = acc;
}

// ------- stage 3: per-graph outer product z z^T -> fp16 (float4-vectorized) --
#define ZROW 132   // LAT + 4 pad: float4-aligned rows, verified conflict-free
__global__ __launch_bounds__(128) void k_outer() {
    __shared__ float Zs[NN * ZROW];
    int b = blockIdx.x >> 1, half = blockIdx.x & 1;
    int tid = threadIdx.x;                  // 128 threads
    // fill: 80*128 floats = 2560 float4
    const float4* src = (const float4*)(g_z + b * NN * LAT);
#pragma unroll
    for (int i = 0; i < 20; i++) {
        int idx = tid + i * 128;            // float4 index
        int row = idx >> 5, c4 = idx & 31;
        *(float4*)&Zs[row * ZROW + c4 * 4] = src[idx];
    }
    __syncthreads();
    int rn = (tid >> 3) * 5;                // 16 positions: rows 0..75
    int rm = half * 40 + (tid & 7) * 5;     // 8 positions per half
    float acc[5][5] = {};
    for (int l = 0; l < LAT; l += 4) {
        float4 a[5], bb[5];
#pragma unroll
        for (int i = 0; i < 5; i++) a[i]  = *(const float4*)&Zs[(rn + i) * ZROW + l];
#pragma unroll
        for (int j = 0; j < 5; j++) bb[j] = *(const float4*)&Zs[(rm + j) * ZROW + l];
#pragma unroll
        for (int i = 0; i < 5; i++)
#pragma unroll
            for (int j = 0; j < 5; j++) {
                acc[i][j] += a[i].x * bb[j].x + a[i].y * bb[j].y
                           + a[i].z * bb[j].z + a[i].w * bb[j].w;
            }
    }
#pragma unroll
    for (int i = 0; i < 5; i++)
#pragma unroll
        for (int j = 0; j < 5; j++)
            g_z2h[b * N2 + (rn + i) * NN + (rm + j)] = __float2half(acc[i][j]);
}

// ======================= fp16 mma.sync GEMM (fp32 acc) =======================
__device__ __forceinline__ uint32_t sptr(const void* p) {
    return (uint32_t)__cvta_generic_to_shared(p);
}
__device__ __forceinline__ void cp16(uint32_t s, const void* g) {
    asm volatile("cp.async.cg.shared.global [%0], [%1], 16;" :: "r"(s), "l"(g));
}
__device__ __forceinline__ void mma16(float* c, const uint32_t* a, const uint32_t* b) {
    asm volatile(
        "mma.sync.aligned.m16n8k16.row.col.f32.f16.f16.f32 "
        "{%0,%1,%2,%3}, {%4,%5,%6,%7}, {%8,%9}, {%0,%1,%2,%3};"
        : "+f"(c[0]), "+f"(c[1]), "+f"(c[2]), "+f"(c[3])
        : "r"(a[0]), "r"(a[1]), "r"(a[2]), "r"(a[3]), "r"(b[0]), "r"(b[1]));
}
__device__ __forceinline__ uint32_t packh2(float lo, float hi) {
    __half2 h = __floats2half2_rn(lo, hi);
    return *(uint32_t*)&h;
}

// smem (4 stages), K_CHUNK = 16:
//   A: fp16, 64 rows x 40 halves (16 used + 24 pad) = 80B/row -> 5120B/stage
//   B: fp32, 16 rows x 260 floats (256 used + 4 pad) = 1040B/row -> 16640B/stage
#define A_STGB  5120
#define B_ROWF  260
#define B_STGB  16640
#define B_OFFB  (4 * A_STGB)
#define MM_SMEM (4 * A_STGB + 4 * B_STGB)   // 87040 bytes

// CTA: 64(M) x 256(N), 8 warps (2x4), warp tile 32x64, K_CHUNK=16, 4 stages.
template<int MODE>
__global__ __launch_bounds__(256, 2) void k_mm(const float* __restrict__ W) {
    constexpr int K    = (MODE == 1) ? N2 : H1;
    constexpr int NOUT = (MODE == 1) ? H1 : N2;
    constexpr int NSPL = (MODE == 1) ? 6 : 12;   // 300 CTAs each (proven)
    const __half* A = (MODE == 1) ? g_z2h : g_z3h;
    float* outp     = (MODE == 1) ? g_p1[blockIdx.y] : g_p2[blockIdx.y];

    extern __shared__ char smc[];
    char* Ab = smc;
    char* Bb = smc + B_OFFB;

    const int tid = threadIdx.x;
    const int n0  = blockIdx.x * 256;
    const int sp  = blockIdx.y;

    constexpr int TOT = K / 16;
    constexpr int per = TOT / NSPL, rem = TOT % NSPL;
    const int ks0 = sp * per + min(sp, rem);
    const int cnt = per + (sp < rem ? 1 : 0);

    const int lane = tid & 31, wp = tid >> 5;
    const int wm = wp >> 2, wn = wp & 3;      // 2 x 4 warp grid
    const int gq = lane >> 2, tq = lane & 3;

    const int a_r = tid >> 1, a_ch = tid & 1;
    const uint32_t a_base = sptr(Ab);
    const uint32_t b_base = sptr(Bb);

    auto issue = [&](int st, int ki) {
        int kk = (ks0 + ki) * 16;
        if (tid < 128)
            cp16(a_base + (uint32_t)(st * A_STGB + a_r * 80 + a_ch * 16),
                 A + (size_t)a_r * K + kk + a_ch * 8);
#pragma unroll
        for (int q = 0; q < 4; q++) {
            int id = tid + q * 256;
            int r  = id >> 6, c4 = (id & 63) * 4;
            cp16(b_base + (uint32_t)(st * B_STGB + (r * B_ROWF + c4) * 4),
                 W + (size_t)(kk + r) * NOUT + n0 + c4);
        }
    };

    float C[2][8][4] = {};

    issue(0, 0); asm volatile("cp.async.commit_group;");
    if (cnt > 1) issue(1, 1);
    asm volatile("cp.async.commit_group;");
    if (cnt > 2) issue(2, 2);
    asm volatile("cp.async.commit_group;");

    for (int i = 0; i < cnt; i++) {
        asm volatile("cp.async.wait_group 2;");
        __syncthreads();
        const int st = i & 3;
        const char*  ab = Ab + st * A_STGB;
        const float* bs = (const float*)(Bb + st * B_STGB);

        uint32_t a[2][4], b[8][2];
#pragma unroll
        for (int mi = 0; mi < 2; mi++) {
            int r = wm * 32 + mi * 16 + gq;
            a[mi][0] = *(const uint32_t*)(ab + r * 80 + tq * 4);
            a[mi][1] = *(const uint32_t*)(ab + (r + 8) * 80 + tq * 4);
            a[mi][2] = *(const uint32_t*)(ab + r * 80 + 16 + tq * 4);
            a[mi][3] = *(const uint32_t*)(ab + (r + 8) * 80 + 16 + tq * 4);
        }
#pragma unroll
        for (int ni = 0; ni < 8; ni++) {
            int c = wn * 64 + ni * 8 + gq;
            b[ni][0] = packh2(bs[(2 * tq) * B_ROWF + c],     bs[(2 * tq + 1) * B_ROWF + c]);
            b[ni][1] = packh2(bs[(2 * tq + 8) * B_ROWF + c], bs[(2 * tq + 9) * B_ROWF + c]);
        }
#pragma unroll
        for (int mi = 0; mi < 2; mi++)
#pragma unroll
            for (int ni = 0; ni < 8; ni++)
                mma16(C[mi][ni], a[mi], b[ni]);

        int nx = i + 3;
        if (nx < cnt) issue(nx & 3, nx);
        asm volatile("cp.async.commit_group;");
    }

    // write split-K partials (summed in epilogue)
#pragma unroll
    for (int mi = 0; mi < 2; mi++)
#pragma unroll
        for (int ni = 0; ni < 8; ni++) {
            int r = wm * 32 + mi * 16 + gq;
            int c = n0 + wn * 64 + ni * 8 + 2 * tq;
            *(float2*)&outp[(size_t)r * NOUT + c]       = make_float2(C[mi][ni][0], C[mi][ni][1]);
            *(float2*)&outp[(size_t)(r + 8) * NOUT + c] = make_float2(C[mi][ni][2], C[mi][ni][3]);
        }
}

// ---------------- epilogues ----------------
__global__ void k_epi1(const float* __restrict__ b1) {
    int g = blockIdx.x * 256 + threadIdx.x;      // float4 index
    int e = g * 4;
    float4 v = *(const float4*)&g_p1[0][e];
#pragma unroll
    for (int s = 1; s < 6; s++) {
        float4 p = *(const float4*)&g_p1[s][e];
        v.x += p.x; v.y += p.y; v.z += p.z; v.w += p.w;
    }
    float4 bb = *(const float4*)&b1[e % H1];
    v.x = fmaxf(v.x + bb.x, 0.f); v.y = fmaxf(v.y + bb.y, 0.f);
    v.z = fmaxf(v.z + bb.z, 0.f); v.w = fmaxf(v.w + bb.w, 0.f);
    __half2 h01 = __floats2half2_rn(v.x, v.y);
    __half2 h23 = __floats2half2_rn(v.z, v.w);
    uint2 pk = make_uint2(*(uint32_t*)&h01, *(uint32_t*)&h23);
    *(uint2*)&g_z3h[e] = pk;
}
// epi2 also resets g_cur for the next replay (blocks 400-419)
__global__ void k_epi2(const float* __restrict__ b2, float* __restrict__ out) {
    if (blockIdx.x >= 400) {
        int i = (blockIdx.x - 400) * 256 + threadIdx.x;
        if (i < N_NODES) g_cur[i] = 0;
        return;
    }
    int g = blockIdx.x * 256 + threadIdx.x;
    int e = g * 4;
    float4 v = *(const float4*)&g_p2[0][e];
#pragma unroll
    for (int s = 1; s < 12; s++) {
        float4 p = *(const float4*)&g_p2[s][e];
        v.x += p.x; v.y += p.y; v.z += p.z; v.w += p.w;
    }
    float4 bb = *(const float4*)&b2[e % N2];
    v.x += bb.x; v.y += bb.y; v.z += bb.z; v.w += bb.w;
    float4 o;
    o.x = 1.f / (1.f + __expf(-v.x));
    o.y = 1.f / (1.f + __expf(-v.y));
    o.z = 1.f / (1.f + __expf(-v.z));
    o.w = 1.f / (1.f + __expf(-v.w));
    *(float4*)&out[e] = o;
}

// ---------------- launch ----------------
extern "C" void kernel_launch(void* const* d_in, const int* in_sizes, int n_in,
                              void* d_out, int out_size) {
    const float* x  = (const float*)d_in[0];
    const int*   ei = (const int*)  d_in[1];
    const float* Wg = (const float*)d_in[2];
    const float* bg = (const float*)d_in[3];
    const float* W1 = (const float*)d_in[4];
    const float* b1 = (const float*)d_in[5];
    const float* W2 = (const float*)d_in[6];
    const float* b2 = (const float*)d_in[7];
    float* out = (float*)d_out;

    static bool attr_done = false;
    if (!attr_done) {
        cudaFuncSetAttribute(k_mm<1>, cudaFuncAttributeMaxDynamicSharedMemorySize, MM_SMEM);
        cudaFuncSetAttribute(k_mm<2>, cudaFuncAttributeMaxDynamicSharedMemorySize, MM_SMEM);
        attr_done = true;
    }

    k_prep  <<<320, 256>>>(x, Wg, ei);            // h-GEMM || CSR build
    k_gather<<<640, 256>>>(bg);
    k_outer <<<128, 128>>>();
    k_mm<1> <<<dim3(50, 6),  256, MM_SMEM>>>(W1); // 300 CTAs @ 2/SM
    k_epi1  <<<NG * H1 / 1024, 256>>>(b1);
    k_mm<2> <<<dim3(25, 12), 256, MM_SMEM>>>(W2); // 300 CTAs @ 2/SM
    k_epi2  <<<420, 256>>>(b2, out);              // + g_cur reset for next call
}